// round 16
// baseline (speedup 1.0000x reference)
#include <cuda_runtime.h>
#include <cuda_fp16.h>
#include <math.h>
#include <stdint.h>

// ---------------- problem constants ----------------
#define NB      32
#define FH      11
#define FW      20
#define NEDGE   42
#define NANG    17
#define NPRED   77
#define NPROP   714
#define NOFF    72
#define KBACK   512
#define KCONV   1024
#define NREG    1241
#define NCLS    34
#define NPAD    1280
#define MROWS   1344
#define MPAD    1408
#define NWORDS  23
#define NSTRIPSF 71.0f
#define NMS_T   15.0f
#define NCHUNK  128
#define NCHUNKS 6
#define KC      32          // K per pipeline chunk (2 k16 mma groups)
#define BSCALE  64.0f
#define BINV    (1.0f / 64.0f)
#define A_SZW   3072        // 128 * 24
#define B_SZW   1536        // 64 * 24
#define STAGEW  9216
#define GEMM_SMEM (2 * STAGEW * 4)   // 73728 bytes
#define KCH     12          // sort transpose chunk

// prep partition (16-float groups): weights only now
#define PREP_W  (NPAD * (KCONV / 16))
#define PREP_S  (KCONV * (KBACK / 16))
#define PREP_TOTAL (PREP_W + PREP_S)

// ---------------- scratch ----------------
__device__ __align__(16) unsigned g_featH16 [MPAD * KBACK / 2];
__device__ __align__(16) unsigned g_featL16 [MPAD * KBACK / 2];
__device__ __align__(16) unsigned g_WconvH16[KCONV * KBACK / 2];
__device__ __align__(16) unsigned g_WconvL16[KCONV * KBACK / 2];
__device__ __align__(16) unsigned g_convH16 [MPAD * KCONV / 2];
__device__ __align__(16) unsigned g_convL16 [MPAD * KCONV / 2];
__device__ __align__(16) unsigned g_WcH16   [NPAD * KCONV / 2];
__device__ __align__(16) unsigned g_WcL16   [NPAD * KCONV / 2];
__device__ float    g_bc    [NPAD];
__device__ float    g_part  [2 * MPAD * NPAD];
__device__ int      g_order [NB * NPROP];
__device__ float    g_sstart[NB * NPROP];
__device__ float    g_send  [NB * NPROP];
__device__ float    g_sxsT  [NB * NOFF * NPROP];   // strip-major: [b][k][rank]
__device__ unsigned g_sup   [NB * NPROP * NWORDS];

// ---------------- helpers ----------------
__device__ __forceinline__ unsigned pack2h(float x0, float x1) {
    __half h0 = __float2half_rn(x0), h1 = __float2half_rn(x1);
    return (unsigned)__half_as_ushort(h0) | ((unsigned)__half_as_ushort(h1) << 16);
}
__device__ __forceinline__ void split16h_store(const float* v, float s,
                                               unsigned* H, unsigned* L) {
    unsigned hw[8], lw[8];
#pragma unroll
    for (int p = 0; p < 8; p++) {
        float x0 = v[2 * p] * s, x1 = v[2 * p + 1] * s;
        __half h0 = __float2half_rn(x0), h1 = __float2half_rn(x1);
        float l0 = x0 - __half2float(h0), l1 = x1 - __half2float(h1);
        hw[p] = (unsigned)__half_as_ushort(h0) | ((unsigned)__half_as_ushort(h1) << 16);
        lw[p] = pack2h(l0, l1);
    }
    *reinterpret_cast<uint4*>(H)     = make_uint4(hw[0], hw[4], hw[1], hw[5]);
    *reinterpret_cast<uint4*>(H + 4) = make_uint4(hw[2], hw[6], hw[3], hw[7]);
    *reinterpret_cast<uint4*>(L)     = make_uint4(lw[0], lw[4], lw[1], lw[5]);
    *reinterpret_cast<uint4*>(L + 4) = make_uint4(lw[2], lw[6], lw[3], lw[7]);
}
__device__ __forceinline__ uint32_t smem_u32(const void* p) {
    uint32_t a;
    asm("{ .reg .u64 tmp; cvta.to.shared.u64 tmp, %1; cvt.u32.u64 %0, tmp; }"
        : "=r"(a) : "l"(p));
    return a;
}
#define MMA_F16(d, a0, a1, a2, a3, b0, b1)                                       \
    asm volatile("mma.sync.aligned.m16n8k16.row.col.f32.f16.f16.f32 "            \
        "{%0,%1,%2,%3}, {%4,%5,%6,%7}, {%8,%9}, {%0,%1,%2,%3};"                  \
        : "+f"((d)[0]), "+f"((d)[1]), "+f"((d)[2]), "+f"((d)[3])                 \
        : "r"(a0), "r"(a1), "r"(a2), "r"(a3), "r"(b0), "r"(b1))
#define CPA_COMMIT() asm volatile("cp.async.commit_group;" ::: "memory")
#define CPA_WAIT1()  asm volatile("cp.async.wait_group 1;" ::: "memory")

// ---------------- prep: pack Wc(x64) + split Wconv(x64) ----------------
__global__ void k_prep(const float* __restrict__ Wr, const float* __restrict__ br,
                       const float* __restrict__ Wc, const float* __restrict__ bc,
                       const float* __restrict__ Wconv) {
    int i = blockIdx.x * blockDim.x + threadIdx.x;
    if (i < PREP_W) {
        int row = i >> 6, k0 = (i & 63) * 16;
        float v[16];
#pragma unroll
        for (int q = 0; q < 16; q++) v[q] = 0.f;
        if (row < NREG) {
#pragma unroll
            for (int q = 0; q < 4; q++)
                *reinterpret_cast<float4*>(v + q * 4) =
                    *reinterpret_cast<const float4*>(&Wr[(size_t)row * KCONV + k0 + q * 4]);
        } else if (row < NREG + NCLS) {
#pragma unroll
            for (int q = 0; q < 4; q++)
                *reinterpret_cast<float4*>(v + q * 4) =
                    *reinterpret_cast<const float4*>(&Wc[(size_t)(row - NREG) * KCONV + k0 + q * 4]);
        }
        size_t o = ((size_t)row * KCONV + k0) >> 1;
        split16h_store(v, BSCALE, &g_WcH16[o], &g_WcL16[o]);
        if (i < NPAD) {
            float b = 0.f;
            if (i < NREG)             b = br[i];
            else if (i < NREG + NCLS) b = bc[i - NREG];
            g_bc[i] = b;
        }
        return;
    }
    i -= PREP_W;
    if (i < PREP_S) {
        size_t o = (size_t)i * 16;
        float v[16];
#pragma unroll
        for (int q = 0; q < 4; q++)
            *reinterpret_cast<float4*>(v + q * 4) =
                *reinterpret_cast<const float4*>(&Wconv[o + q * 4]);
        split16h_store(v, BSCALE, &g_WconvH16[o >> 1], &g_WconvL16[o >> 1]);
    }
}

// ---------------- gather: coalesced feat transpose -> fp16 split pair-words ----------------
// block = (channel chunk of 32, batch); smem-staged.
__global__ __launch_bounds__(256) void k_gather(const float* __restrict__ feat) {
    __shared__ float sf[32][221];
    int b = blockIdx.y, c0 = blockIdx.x * 32;
    int t = threadIdx.x;
    for (int idx = t; idx < 32 * (FH * FW); idx += 256) {
        int ch = idx / (FH * FW), pos = idx % (FH * FW);
        sf[ch][pos] = feat[(size_t)(b * KBACK + c0 + ch) * (FH * FW) + pos];
    }
    __syncthreads();
    for (int item = t; item < NEDGE * 16; item += 256) {
        int e = item >> 4, pw = item & 15;
        int g16 = pw >> 3, p = pw & 7;
        int h, w;
        if (e < FH)        { h = e;      w = 0;        }
        else if (e < 2*FH) { h = e - FH; w = FW - 1;   }
        else               { h = FH - 1; w = e - 2*FH; }
        int hw = h * FW + w;
        float v0 = sf[g16 * 16 + 2 * p][hw];
        float v1 = sf[g16 * 16 + 2 * p + 1][hw];
        __half h0 = __float2half_rn(v0), h1 = __float2half_rn(v1);
        float l0 = v0 - __half2float(h0), l1 = v1 - __half2float(h1);
        int m = b * NEDGE + e;
        int pos = (p < 4) ? 2 * p : 2 * (p - 4) + 1;
        size_t wb = ((size_t)m * KBACK + c0 + g16 * 16) >> 1;
        g_featH16[wb + pos] = (unsigned)__half_as_ushort(h0)
                            | ((unsigned)__half_as_ushort(h1) << 16);
        g_featL16[wb + pos] = pack2h(l0, l1);
    }
}

// ---------------- fp16 mma.sync GEMM, 3-term split, 2-stage cp.async ----------------
// MODE 0: K-split x2 via gridDim.z, write fp32 partials (gemm2)
// MODE 1: no split, fused epilogue: descale+bias -> fp16 split pair-words (gemm1)
template<int MODE>
__global__ __launch_bounds__(256, 3) void k_gemm_f16(
    const unsigned* __restrict__ Ah, const unsigned* __restrict__ Al,
    const unsigned* __restrict__ Bh, const unsigned* __restrict__ Bl,
    float* __restrict__ Cpart, const float* __restrict__ bias,
    unsigned* __restrict__ Ch, unsigned* __restrict__ Cl,
    int K, int N)
{
    extern __shared__ unsigned smw[];
    const uint32_t sbase = smem_u32(smw);
    const int m0 = blockIdx.y * 128, n0 = blockIdx.x * 64;
    const int t = threadIdx.x, w = t >> 5, lane = t & 31;
    const int g = lane >> 2, c = lane & 3;
    const int wm = w >> 1, wn = w & 1;
    const int Kw = K >> 1;
    const int kbase = (MODE == 0) ? blockIdx.z * (K / 2) : 0;
    const int nch = ((MODE == 0) ? (K / 2) : K) / KC;

    const unsigned* srcA[2] = { Ah + (size_t)m0 * Kw, Al + (size_t)m0 * Kw };
    const unsigned* srcB[2] = { Bh + (size_t)n0 * Kw, Bl + (size_t)n0 * Kw };

    auto issue = [&](int ch, int st) {
        int kbw = (kbase + ch * KC) >> 1;
#pragma unroll
        for (int i = 0; i < 4; i++) {
            int idx = t + (i & 1) * 256;
            int mat = i >> 1;
            int row = idx >> 2, q = idx & 3;
            const unsigned* src = srcA[mat] + (size_t)row * Kw + kbw + q * 4;
            uint32_t dst = sbase + (uint32_t)((st * STAGEW + mat * A_SZW + row * 24 + q * 4) << 2);
            asm volatile("cp.async.cg.shared.global [%0], [%1], 16;" :: "r"(dst), "l"(src));
        }
#pragma unroll
        for (int i = 0; i < 2; i++) {
            int mat = i;
            int row = t >> 2, q = t & 3;
            const unsigned* src = srcB[mat] + (size_t)row * Kw + kbw + q * 4;
            uint32_t dst = sbase + (uint32_t)((st * STAGEW + 2 * A_SZW + mat * B_SZW + row * 24 + q * 4) << 2);
            asm volatile("cp.async.cg.shared.global [%0], [%1], 16;" :: "r"(dst), "l"(src));
        }
        CPA_COMMIT();
    };

    float acc[2][4][4];
#pragma unroll
    for (int mt = 0; mt < 2; mt++)
#pragma unroll
        for (int nt = 0; nt < 4; nt++)
#pragma unroll
            for (int e = 0; e < 4; e++) acc[mt][nt][e] = 0.f;

    issue(0, 0);
    issue(1, 1);

    for (int ch = 0; ch < nch; ch++) {
        CPA_WAIT1();
        __syncthreads();
        const unsigned* SW = smw + (ch & 1) * STAGEW;
#pragma unroll
        for (int grp = 0; grp < 2; grp++) {
            const int go = grp * 8 + 2 * c;
            unsigned ahf[2][4], alf[2][4];
#pragma unroll
            for (int mt = 0; mt < 2; mt++) {
                int r = (wm * 32 + mt * 16 + g) * 24 + go;
                uint2 x0 = *reinterpret_cast<const uint2*>(&SW[r]);
                uint2 x1 = *reinterpret_cast<const uint2*>(&SW[r + 192]);
                ahf[mt][0] = x0.x; ahf[mt][1] = x1.x; ahf[mt][2] = x0.y; ahf[mt][3] = x1.y;
                uint2 y0 = *reinterpret_cast<const uint2*>(&SW[r + A_SZW]);
                uint2 y1 = *reinterpret_cast<const uint2*>(&SW[r + A_SZW + 192]);
                alf[mt][0] = y0.x; alf[mt][1] = y1.x; alf[mt][2] = y0.y; alf[mt][3] = y1.y;
            }
            uint2 bhf[4], blf[4];
#pragma unroll
            for (int nt = 0; nt < 4; nt++) {
                int n = (wn * 32 + nt * 8 + g) * 24 + go;
                bhf[nt] = *reinterpret_cast<const uint2*>(&SW[2 * A_SZW + n]);
                blf[nt] = *reinterpret_cast<const uint2*>(&SW[2 * A_SZW + B_SZW + n]);
            }
#pragma unroll
            for (int mt = 0; mt < 2; mt++)
#pragma unroll
                for (int nt = 0; nt < 4; nt++)
                    MMA_F16(acc[mt][nt], ahf[mt][0], ahf[mt][1], ahf[mt][2], ahf[mt][3],
                            bhf[nt].x, bhf[nt].y);
#pragma unroll
            for (int mt = 0; mt < 2; mt++)
#pragma unroll
                for (int nt = 0; nt < 4; nt++)
                    MMA_F16(acc[mt][nt], ahf[mt][0], ahf[mt][1], ahf[mt][2], ahf[mt][3],
                            blf[nt].x, blf[nt].y);
#pragma unroll
            for (int mt = 0; mt < 2; mt++)
#pragma unroll
                for (int nt = 0; nt < 4; nt++)
                    MMA_F16(acc[mt][nt], alf[mt][0], alf[mt][1], alf[mt][2], alf[mt][3],
                            bhf[nt].x, bhf[nt].y);
        }
        __syncthreads();
        if (ch + 2 < nch) issue(ch + 2, ch & 1);
        else CPA_COMMIT();
    }

    if (MODE == 0) {
        float* C = Cpart + (size_t)blockIdx.z * MPAD * N;
#pragma unroll
        for (int mt = 0; mt < 2; mt++) {
            int row0 = m0 + wm * 32 + mt * 16 + g;
#pragma unroll
            for (int nt = 0; nt < 4; nt++) {
                int col = n0 + wn * 32 + nt * 8 + 2 * c;
                *reinterpret_cast<float2*>(&C[(size_t)row0 * N + col])
                    = make_float2(acc[mt][nt][0], acc[mt][nt][1]);
                *reinterpret_cast<float2*>(&C[(size_t)(row0 + 8) * N + col])
                    = make_float2(acc[mt][nt][2], acc[mt][nt][3]);
            }
        }
    } else {
        // fused: v = acc/64 + bias; fp16 hi/lo split; interleaved pair-word store
#pragma unroll
        for (int mt = 0; mt < 2; mt++) {
            int row0 = m0 + wm * 32 + mt * 16 + g;
#pragma unroll
            for (int nt = 0; nt < 4; nt++) {
                int col = n0 + wn * 32 + nt * 8 + 2 * c;
                float b0 = bias[col], b1 = bias[col + 1];
                int pos = 2 * c + (nt & 1);
                size_t gbase = (size_t)(col & ~15);
#pragma unroll
                for (int r = 0; r < 2; r++) {
                    int row = row0 + r * 8;
                    float v0 = acc[mt][nt][r * 2 + 0] * BINV + b0;
                    float v1 = acc[mt][nt][r * 2 + 1] * BINV + b1;
                    __half h0 = __float2half_rn(v0), h1 = __float2half_rn(v1);
                    float l0 = v0 - __half2float(h0), l1 = v1 - __half2float(h1);
                    size_t wb = (((size_t)row * N + gbase) >> 1) + pos;
                    Ch[wb] = (unsigned)__half_as_ushort(h0)
                           | ((unsigned)__half_as_ushort(h1) << 16);
                    Cl[wb] = pack2h(l0, l1);
                }
            }
        }
    }
}

// ---------------- assemble (inline K-split reduce + descale of gemm2 partials) ----------------
__global__ __launch_bounds__(544) void k_assemble(const float* __restrict__ anchd,
                                                  float* __restrict__ out) {
    int row = blockIdx.x;
    int b = row / NEDGE, e = row % NEDGE;
    float* prop   = out + (size_t)b * NPROP * NPRED;
    float* scores = out + (size_t)NB * NPROP * NPRED + (size_t)NB * NPROP + (size_t)b * NPROP;
    const float* p0 = g_part + (size_t)row * NPAD;
    auto rcval = [&](int n) {
        float v = p0[n] + p0[(size_t)MPAD * NPAD + n];
        return v * BINV + g_bc[n];
    };
    int a = threadIdx.x >> 5, lane = threadIdx.x & 31;
    int p = e * NANG + a;
#pragma unroll
    for (int qi = 0; qi < 3; qi++) {
        int q = lane + qi * 32;
        if (q >= NPRED) break;
        float v;
        if (q < 2)      v = rcval(NREG + a * 2 + q);
        else if (q < 4) v = anchd[(size_t)p * NPRED + q];
        else            v = anchd[(size_t)p * NPRED + q] + rcval(a * 73 + (q - 4));
        prop[(size_t)p * NPRED + q] = v;
    }
    if (lane == 0) {
        float l0 = rcval(NREG + a * 2);
        float l1 = rcval(NREG + a * 2 + 1);
        scores[p] = 1.0f / (1.0f + expf(l0 - l1));
    }
}

// ---------------- NMS sort: rank + staged coalesced transpose into xsT ----------------
__global__ __launch_bounds__(736) void k_sort(const float* __restrict__ out) {
    __shared__ float s[NPROP];
    __shared__ int   sorder[NPROP];
    __shared__ float sxbuf[KCH * NPROP];
    int b = blockIdx.x;
    const float* scores = out + (size_t)NB * NPROP * NPRED + (size_t)NB * NPROP + (size_t)b * NPROP;
    const float* prop   = out + (size_t)b * NPROP * NPRED;
    int t = threadIdx.x;
    if (t < NPROP) s[t] = scores[t];
    __syncthreads();
    if (t < NPROP) {
        float si = s[t];
        int r = 0;
        for (int j = 0; j < NPROP; j++) {
            float sj = s[j];
            r += (sj > si) || (sj == si && j < t);
        }
        int base = b * NPROP;
        g_order[base + r] = t;
        sorder[r] = t;
        float p2 = prop[(size_t)t * NPRED + 2];
        float p4 = prop[(size_t)t * NPRED + 4];
        float st = fminf(fmaxf(rintf(p2 * NSTRIPSF), 0.0f), NSTRIPSF);
        float en = fminf(fmaxf(st + p4 - 1.0f, 0.0f), NSTRIPSF);
        g_sstart[base + r] = st;
        g_send[base + r]   = en;
    }
    __syncthreads();
    float* xsT = g_sxsT + (size_t)b * NOFF * NPROP;
    for (int k0 = 0; k0 < NOFF; k0 += KCH) {
        for (int idx = t; idx < NPROP * KCH; idx += 736) {
            int i = idx / KCH, kk = idx % KCH;
            sxbuf[kk * NPROP + i] = prop[(size_t)i * NPRED + 5 + k0 + kk];
        }
        __syncthreads();
        for (int idx = t; idx < KCH * NPROP; idx += 736) {
            int kk = idx / NPROP, r = idx % NPROP;
            xsT[(size_t)(k0 + kk) * NPROP + r] = sxbuf[kk * NPROP + sorder[r]];
        }
        __syncthreads();
    }
}

// ---------------- NMS pairs: coalesced strip-major reads ----------------
__global__ void k_pairs() {
    int b    = blockIdx.y;
    int warp = threadIdx.x >> 5;
    int lane = threadIdx.x & 31;
    int i    = blockIdx.x * 8 + warp;
    if (i >= NPROP) return;
    int base = b * NPROP;
    const float* xsT = g_sxsT + (size_t)b * NOFF * NPROP;
    float si = g_sstart[base + i], ei = g_send[base + i];
    for (int jw = 0; jw < NWORDS; jw++) {
        int j = jw * 32 + lane;
        bool sup = false;
        if (j < NPROP) {
            float s  = fmaxf(si, g_sstart[base + j]);
            float e  = fminf(ei, g_send[base + j]);
            float cnt = e - s + 1.0f;
            if (cnt > 0.0f) {
                int k0 = (int)s;
                int k1 = (int)floorf(e);
                float sum = 0.0f;
                for (int k = k0; k <= k1; k++)
                    sum += fabsf(xsT[(size_t)k * NPROP + i] - xsT[(size_t)k * NPROP + j]);
                sup = (sum / fmaxf(cnt, 1.0f)) < NMS_T;
            }
        }
        unsigned m = __ballot_sync(0xFFFFFFFFu, sup);
        if (lane == 0) g_sup[(size_t)(base + i) * NWORDS + jw] = m;
    }
}

// ---------------- NMS scan: sequential, smem-staged ----------------
__global__ __launch_bounds__(256) void k_scan(float* __restrict__ out) {
    int b = blockIdx.x;
    __shared__ unsigned ssup[2][NCHUNK][NWORDS + 1];
    __shared__ int      sorder[NPROP];
    __shared__ float    skeep [NPROP];
    int t = threadIdx.x, lane = t & 31, warp = t >> 5;
    int base = b * NPROP;
    const unsigned* gs = g_sup + (size_t)base * NWORDS;

    for (int i = t; i < NPROP; i += 256) sorder[i] = g_order[base + i];
    for (int x = t; x < NCHUNK * NWORDS; x += 256)
        ssup[0][x / NWORDS][x % NWORDS] = gs[x];
    __syncthreads();

    unsigned my = 0;
    for (int c = 0; c < NCHUNKS; c++) {
        if (warp != 0) {
            if (c + 1 < NCHUNKS) {
                int i0 = (c + 1) * NCHUNK;
                int cnt = min(NCHUNK, NPROP - i0) * NWORDS;
                int tt = t - 32;
                for (int x = tt; x < cnt; x += 224)
                    ssup[(c + 1) & 1][x / NWORDS][x % NWORDS] = gs[(size_t)i0 * NWORDS + x];
            }
        } else {
            int i1 = min(NPROP, (c + 1) * NCHUNK);
            int lw = (lane < NWORDS) ? lane : 0;
            for (int i = c * NCHUNK; i < i1; i++) {
                unsigned row = ssup[c & 1][i - c * NCHUNK][lw];
                int wi = i >> 5, bit = i & 31;
                unsigned wsup = __shfl_sync(0xFFFFFFFFu, my, wi);
                bool kept = ((wsup >> bit) & 1u) == 0u;
                if (kept) {
                    unsigned m;
                    if (lane > wi)       m = 0xFFFFFFFFu;
                    else if (lane == wi) m = (bit == 31) ? 0u : (0xFFFFFFFFu << (bit + 1));
                    else                 m = 0u;
                    my |= row & m;
                }
                if (lane == 0) skeep[sorder[i]] = kept ? 1.0f : 0.0f;
            }
        }
        __syncthreads();
    }
    float* keep = out + (size_t)NB * NPROP * NPRED + (size_t)b * NPROP;
    for (int i = t; i < NPROP; i += 256) keep[i] = skeep[i];
}

// ---------------- launcher ----------------
extern "C" void kernel_launch(void* const* d_in, const int* in_sizes, int n_in,
                              void* d_out, int out_size) {
    const float* feat   = (const float*)d_in[0];
    const float* W_conv = (const float*)d_in[1];
    const float* b_conv = (const float*)d_in[2];
    const float* W_cls  = (const float*)d_in[3];
    const float* b_cls  = (const float*)d_in[4];
    const float* W_reg  = (const float*)d_in[5];
    const float* b_reg  = (const float*)d_in[6];
    const float* anchd  = (const float*)d_in[8];
    float* out = (float*)d_out;

    void *pFH, *pFL, *pWH, *pWL, *pCH, *pCL, *pWcH, *pWcL, *pPart;
    cudaGetSymbolAddress(&pFH,  g_featH16);
    cudaGetSymbolAddress(&pFL,  g_featL16);
    cudaGetSymbolAddress(&pWH,  g_WconvH16);
    cudaGetSymbolAddress(&pWL,  g_WconvL16);
    cudaGetSymbolAddress(&pCH,  g_convH16);
    cudaGetSymbolAddress(&pCL,  g_convL16);
    cudaGetSymbolAddress(&pWcH, g_WcH16);
    cudaGetSymbolAddress(&pWcL, g_WcL16);
    cudaGetSymbolAddress(&pPart, g_part);

    cudaFuncSetAttribute(k_gemm_f16<0>, cudaFuncAttributeMaxDynamicSharedMemorySize, GEMM_SMEM);
    cudaFuncSetAttribute(k_gemm_f16<1>, cudaFuncAttributeMaxDynamicSharedMemorySize, GEMM_SMEM);

    k_prep<<<(PREP_TOTAL + 255) / 256, 256>>>(W_reg, b_reg, W_cls, b_cls, W_conv);
    k_gather<<<dim3(KBACK / 32, NB), 256>>>(feat);

    // GEMM1 (fused epilogue): feat @ (64*W_conv)^T -> conv fp16 h/l directly
    k_gemm_f16<1><<<dim3(KCONV / 64, MPAD / 128, 1), 256, GEMM_SMEM>>>(
        (const unsigned*)pFH, (const unsigned*)pFL,
        (const unsigned*)pWH, (const unsigned*)pWL,
        nullptr, b_conv, (unsigned*)pCH, (unsigned*)pCL, KBACK, KCONV);

    // GEMM2 (K-split x2): conv @ (64*Wc)^T -> partials (reduced + descaled in assemble)
    k_gemm_f16<0><<<dim3(NPAD / 64, MPAD / 128, 2), 256, GEMM_SMEM>>>(
        (const unsigned*)pCH, (const unsigned*)pCL,
        (const unsigned*)pWcH, (const unsigned*)pWcL,
        (float*)pPart, nullptr, nullptr, nullptr, KCONV, NPAD);

    k_assemble<<<MROWS, 544>>>(anchd, out);
    k_sort<<<NB, 736>>>(out);
    k_pairs<<<dim3((NPROP + 7) / 8, NB), 256>>>();
    k_scan<<<NB, 256>>>(out);
}